// round 8
// baseline (speedup 1.0000x reference)
#include <cuda_runtime.h>
#include <cuda_fp16.h>
#include <cstdint>

#define B_     8
#define N_     4096
#define D_     1024
#define EMB_   64
#define CLN_   10
#define TILE_M 64
#define KC_    32                  // k-chunk
#define NCHUNK (D_ / KC_)          // 32
#define NTHR   256
#define NCTA_X (N_ / TILE_M)       // 64 CTAs per batch
#define PSTRIDE 656
#define NSTAGE 3

// ---------------- device scratch (allocation-free rule) ----------------
__device__ float g_part[B_ * NCTA_X * PSTRIDE];
__device__ int   g_done[B_];                      // zero-init; self-resetting
__device__ __align__(16) __half g_W1hi[EMB_ * D_];
__device__ __align__(16) __half g_W1lo[EMB_ * D_];

// ---------------- dynamic smem layout (bytes) ----------------
#define SM_B1S    0                // 64 f
#define SM_LABS   256              // 64 int
#define SM_CSUM   512              // 2 x 640 f -> ends 5632
#define SM_STAGE  6144             // stages: A 8KB + B 8KB each
#define STAGE_SZ  16384
#define B_OFF     8192             // within stage: B hi 4KB @+8192, lo 4KB @+12288
#define BLO_OFF   4096
#define SMEM_TOTAL (SM_STAGE + NSTAGE * STAGE_SZ)   // 55296 -> 4 CTAs/SM

__device__ __forceinline__ uint32_t smem_u32(const void* p) {
    uint32_t a;
    asm("{ .reg .u64 t; cvta.to.shared.u64 t, %1; cvt.u32.u64 %0, t; }" : "=r"(a) : "l"(p));
    return a;
}
__device__ __forceinline__ uint32_t sw64(uint32_t o) { return o ^ ((o >> 3) & 0x30); }
// A swizzle: 128B fp32 rows, 16B unit q XORed with row%8
__device__ __forceinline__ uint32_t aswz(int rr, int cb) {
    int q = cb >> 4;
    return (uint32_t)(rr * 128 + (((q ^ (rr & 7)) << 4) | (cb & 15)));
}

__device__ __forceinline__ void ldmx4(uint32_t* r, uint32_t addr) {
    asm volatile("ldmatrix.sync.aligned.m8n8.x4.shared.b16 {%0,%1,%2,%3}, [%4];"
                 : "=r"(r[0]), "=r"(r[1]), "=r"(r[2]), "=r"(r[3]) : "r"(addr));
}
__device__ __forceinline__ void mma16816(float* c, const uint32_t* a, uint32_t b0, uint32_t b1) {
    asm volatile("mma.sync.aligned.m16n8k16.row.col.f32.f16.f16.f32 "
                 "{%0,%1,%2,%3}, {%4,%5,%6,%7}, {%8,%9}, {%0,%1,%2,%3};"
                 : "+f"(c[0]), "+f"(c[1]), "+f"(c[2]), "+f"(c[3])
                 : "r"(a[0]), "r"(a[1]), "r"(a[2]), "r"(a[3]), "r"(b0), "r"(b1));
}
__device__ __forceinline__ void cpasync16(uint32_t saddr, const void* gaddr) {
    asm volatile("cp.async.cg.shared.global [%0], [%1], 16;" :: "r"(saddr), "l"(gaddr));
}

// ---------------------------------------------------------------------------
// Kernel 0: split-convert W1 to fp16 hi/lo (vectorized)
// ---------------------------------------------------------------------------
__global__ void init_kernel(const float* __restrict__ W1) {
    int i4 = blockIdx.x * 256 + threadIdx.x;
    float4 v = *(const float4*)(W1 + (size_t)i4 * 4);
    __half2 h0 = __floats2half2_rn(v.x, v.y);
    __half2 h1 = __floats2half2_rn(v.z, v.w);
    float2 f0 = __half22float2(h0), f1 = __half22float2(h1);
    __half2 l0 = __floats2half2_rn(v.x - f0.x, v.y - f0.y);
    __half2 l1 = __floats2half2_rn(v.z - f1.x, v.w - f1.y);
    uint2 hv, lv;
    hv.x = *(uint32_t*)&h0; hv.y = *(uint32_t*)&h1;
    lv.x = *(uint32_t*)&l0; lv.y = *(uint32_t*)&l1;
    *(uint2*)(g_W1hi + (size_t)i4 * 4) = hv;
    *(uint2*)(g_W1lo + (size_t)i4 * 4) = lv;
}

// ---------------------------------------------------------------------------
// Fused kernel: 8 warps, N-split (each warp 16 rows x 32 cols), A+B via
// 3-stage cp.async, 3-term fp16-split mma.sync; last CTA per batch runs head.
// ---------------------------------------------------------------------------
__global__ void __launch_bounds__(NTHR, 4)
fused_kernel(const float* __restrict__ data,
             const int*   __restrict__ labels,
             const float* __restrict__ b1,
             const float* __restrict__ Wa1, const float* __restrict__ ba1,
             const float* __restrict__ Wa2, const float* __restrict__ ba2,
             const float* __restrict__ Wf1, const float* __restrict__ bf1,
             const float* __restrict__ Wf2, const float* __restrict__ bf2,
             float* __restrict__ out) {
    extern __shared__ char smem[];
    const uint32_t sb = smem_u32(smem);
    const int tid  = threadIdx.x;
    const int warp = tid >> 5;
    const int lane = tid & 31;
    const int wm   = warp & 3;        // m-group: rows wm*16..+15
    const int wn   = warp >> 2;       // n-group: cols wn*32..+31
    const int b    = blockIdx.y;
    const int bx   = blockIdx.x;
    const int p0   = bx * TILE_M;

    float* b1s  = (float*)(smem + SM_B1S);
    int*   labs = (int*)  (smem + SM_LABS);
    float* csum = (float*)(smem + SM_CSUM);

    if (tid < EMB_)   b1s[tid]  = b1[tid];
    if (tid < TILE_M) labs[tid] = labels[b * N_ + p0 + tid];
    for (int i = tid; i < 2 * CLN_ * EMB_; i += NTHR) csum[i] = 0.0f;

    const float* dbase = data + (size_t)(b * N_ + p0) * D_;

    // per-chunk cooperative fill: A 512 x 16B units, B 256+256 units
    const int a_r = tid >> 3, a_q = tid & 7;      // with l offset below
    const int b_r = tid >> 2, b_q = tid & 3;
    auto issueChunk = [&](int chunk) {
        const int kc = chunk * KC_;
        const uint32_t st = sb + SM_STAGE + (chunk % NSTAGE) * STAGE_SZ;
#pragma unroll
        for (int l = 0; l < 2; l++) {             // A: 64 rows x 128B fp32
            int r = a_r + l * 32;
            cpasync16(st + aswz(r, a_q * 16), dbase + (size_t)r * D_ + kc + a_q * 4);
        }
        {                                          // B hi + lo: 64 rows x 64B
            uint32_t sw = sw64((uint32_t)(b_r * 64 + b_q * 16));
            cpasync16(st + B_OFF + sw,           g_W1hi + (size_t)b_r * D_ + kc + b_q * 8);
            cpasync16(st + B_OFF + BLO_OFF + sw, g_W1lo + (size_t)b_r * D_ + kc + b_q * 8);
        }
        asm volatile("cp.async.commit_group;");
    };

    issueChunk(0);
    issueChunk(1);

    float acc[4][4];
#pragma unroll
    for (int nt = 0; nt < 4; nt++)
#pragma unroll
        for (int i = 0; i < 4; i++) acc[nt][i] = 0.0f;

    const int rr1 = wm * 16 + (lane >> 2);
    const int rr2 = rr1 + 8;
    const int cb_l = (lane & 3) * 8;
    const uint32_t brow8 = (uint32_t)(((lane >> 4) & 1) * 8 + (lane & 7));
    const uint32_t bkb   = (uint32_t)(((lane >> 3) & 1) * 16);

    for (int c = 0; c < NCHUNK; c++) {
        asm volatile("cp.async.wait_group 1;");
        __syncthreads();                          // chunk c visible; stage (c-1) free

        if (c + 2 < NCHUNK) issueChunk(c + 2);
        else asm volatile("cp.async.commit_group;");   // uniform group count

        const uint32_t st = sb + SM_STAGE + (c % NSTAGE) * STAGE_SZ;
        const char* abuf = smem + SM_STAGE + (c % NSTAGE) * STAGE_SZ;

#pragma unroll
        for (int ks = 0; ks < 2; ks++) {
            const int cb0 = ks * 64 + cb_l;
            float2 v00 = *(const float2*)(abuf + aswz(rr1, cb0));
            float2 v10 = *(const float2*)(abuf + aswz(rr2, cb0));
            float2 v01 = *(const float2*)(abuf + aswz(rr1, cb0 + 32));
            float2 v11 = *(const float2*)(abuf + aswz(rr2, cb0 + 32));
            __half2 h00 = __floats2half2_rn(v00.x, v00.y);
            __half2 h10 = __floats2half2_rn(v10.x, v10.y);
            __half2 h01 = __floats2half2_rn(v01.x, v01.y);
            __half2 h11 = __floats2half2_rn(v11.x, v11.y);
            float2 f00 = __half22float2(h00), f10 = __half22float2(h10);
            float2 f01 = __half22float2(h01), f11 = __half22float2(h11);
            __half2 e00 = __floats2half2_rn(v00.x - f00.x, v00.y - f00.y);
            __half2 e10 = __floats2half2_rn(v10.x - f10.x, v10.y - f10.y);
            __half2 e01 = __floats2half2_rn(v01.x - f01.x, v01.y - f01.y);
            __half2 e11 = __floats2half2_rn(v11.x - f11.x, v11.y - f11.y);
            uint32_t ah[4] = { *(uint32_t*)&h00, *(uint32_t*)&h10,
                               *(uint32_t*)&h01, *(uint32_t*)&h11 };
            uint32_t al[4] = { *(uint32_t*)&e00, *(uint32_t*)&e10,
                               *(uint32_t*)&e01, *(uint32_t*)&e11 };
#pragma unroll
            for (int j = 0; j < 2; j++) {         // 2 n16-tiles per warp
                uint32_t bh[4], bl[4];
                uint32_t boff = sw64((uint32_t)(wn * 32 + j * 16 + (int)brow8) * 64 +
                                     (uint32_t)(ks * 32) + bkb);
                ldmx4(bh, st + B_OFF + boff);
                ldmx4(bl, st + B_OFF + BLO_OFF + boff);
                mma16816(acc[2 * j],     ah, bh[0], bh[1]);
                mma16816(acc[2 * j],     ah, bl[0], bl[1]);
                mma16816(acc[2 * j],     al, bh[0], bh[1]);
                mma16816(acc[2 * j + 1], ah, bh[2], bh[3]);
                mma16816(acc[2 * j + 1], ah, bl[2], bl[3]);
                mma16816(acc[2 * j + 1], al, bh[2], bh[3]);
            }
        }
        __syncthreads();                          // all reads done before refill
    }

    // ---- epilogue: bias + ReLU -> e-tile (64 x 66, reuse stage region) ----
    float* etile = (float*)(smem + SM_STAGE);
    __syncthreads();
    {
        int r0 = wm * 16 + (lane >> 2);
        int cq = 2 * (lane & 3);
#pragma unroll
        for (int j = 0; j < 2; j++)
#pragma unroll
            for (int s = 0; s < 2; s++) {
                int col = wn * 32 + j * 16 + s * 8 + cq;
                int ai  = 2 * j + s;
                float bv0 = b1s[col], bv1 = b1s[col + 1];
                etile[r0 * 66 + col]           = fmaxf(acc[ai][0] + bv0, 0.0f);
                etile[r0 * 66 + col + 1]       = fmaxf(acc[ai][1] + bv1, 0.0f);
                etile[(r0 + 8) * 66 + col]     = fmaxf(acc[ai][2] + bv0, 0.0f);
                etile[(r0 + 8) * 66 + col + 1] = fmaxf(acc[ai][3] + bv1, 0.0f);
            }
    }
    __syncthreads();

    {   // split-row segment reduction, no atomics (threads 0-63 and 128-191)
        if (((tid >> 6) & 1) == 0) {
            int half = tid >> 7;
            int e    = tid & 63;
            float* cs = csum + half * (CLN_ * EMB_);
            int rbase = half * 32;
            for (int r = 0; r < 32; r++) {
                int row = rbase + r;
                cs[labs[row] * EMB_ + e] += etile[row * 66 + e];
            }
        }
    }
    __syncthreads();

    float* prow = g_part + ((size_t)b * NCTA_X + bx) * PSTRIDE;
    for (int i = tid; i < CLN_ * EMB_; i += NTHR)
        prow[i] = csum[i] + csum[CLN_ * EMB_ + i];
    if (tid < CLN_) {
        int cnt = 0;
        for (int r = 0; r < TILE_M; r++) cnt += (labs[r] == tid);
        prow[640 + tid] = (float)cnt;
    }
    __threadfence();
    __syncthreads();

    // ---- last CTA of this batch runs the head ----
    __shared__ int s_last;
    if (tid == 0) s_last = (atomicAdd(&g_done[b], 1) == NCTA_X - 1) ? 1 : 0;
    __syncthreads();
    if (!s_last) return;
    __threadfence();

    float* hc    = (float*)(smem + SM_STAGE);
    float* h     = hc + 656;
    float* u     = h + 640;
    float* score = u + 320;
    float* Avec  = score + 16;
    float* mask  = Avec + 16;
    float* Mv    = mask + 16;
    float* f     = Mv + 64;

    for (int i = tid; i < 650; i += NTHR) {
        float s = 0.0f;
        const float* base = g_part + (size_t)b * NCTA_X * PSTRIDE + i;
#pragma unroll
        for (int j = 0; j < NCTA_X; j++) s += base[j * PSTRIDE];
        hc[i] = s;
    }
    __syncthreads();

    if (tid < EMB_) {
        for (int c = 0; c < CLN_; c++)
            h[c * EMB_ + tid] = hc[c * EMB_ + tid] / fmaxf(hc[640 + c], 1.0f);
    }
    if (tid < CLN_) mask[tid] = (hc[640 + tid] > 0.0f) ? 1.0f : 0.0f;
    __syncthreads();

    if (tid < 32) {
        for (int c = 0; c < CLN_; c++) {
            float s = ba1[tid];
            for (int e = 0; e < EMB_; e++) s += h[c * EMB_ + e] * Wa1[tid * EMB_ + e];
            u[c * 32 + tid] = tanhf(s);
        }
    }
    __syncthreads();

    if (tid < CLN_) {
        float s = ba2[0];
        for (int k = 0; k < 32; k++) s += u[tid * 32 + k] * Wa2[k];
        score[tid] = s;
    }
    __syncthreads();

    if (tid == 0) {
        float xmax = -1e30f;
        for (int c = 0; c < CLN_; c++) {
            float xm = score[c] * mask[c] + (1.0f - 1.0f / (mask[c] + 1e-5f));
            xmax = fmaxf(xmax, xm);
        }
        float ssum = 0.0f;
        for (int c = 0; c < CLN_; c++) {
            float ex = expf(score[c] - xmax) * mask[c];
            Avec[c] = ex;
            ssum += ex;
        }
        for (int c = 0; c < CLN_; c++) Avec[c] /= ssum;
    }
    __syncthreads();

    if (tid < EMB_) {
        float m = 0.0f;
        for (int c = 0; c < CLN_; c++) m += Avec[c] * h[c * EMB_ + tid];
        Mv[tid] = m;
    }
    __syncthreads();

    if (tid < 32) {
        float s = bf1[tid];
        for (int e = 0; e < EMB_; e++) s += Mv[e] * Wf1[tid * EMB_ + e];
        f[tid] = fmaxf(s, 0.0f);
    }
    __syncthreads();

    if (tid == 0) {
        float s = bf2[0];
        for (int k = 0; k < 32; k++) s += f[k] * Wf2[k];
        out[b] = s;
        g_done[b] = 0;      // reset for next graph replay
    }
}

// ---------------------------------------------------------------------------
extern "C" void kernel_launch(void* const* d_in, const int* in_sizes, int n_in,
                              void* d_out, int out_size) {
    const float* data   = (const float*)d_in[0];
    const int*   labels = (const int*)  d_in[1];
    const float* W1     = (const float*)d_in[2];
    const float* b1     = (const float*)d_in[3];
    const float* Wa1    = (const float*)d_in[4];
    const float* ba1    = (const float*)d_in[5];
    const float* Wa2    = (const float*)d_in[6];
    const float* ba2    = (const float*)d_in[7];
    const float* Wf1    = (const float*)d_in[8];
    const float* bf1    = (const float*)d_in[9];
    const float* Wf2    = (const float*)d_in[10];
    const float* bf2    = (const float*)d_in[11];

    cudaFuncSetAttribute(fused_kernel, cudaFuncAttributeMaxDynamicSharedMemorySize,
                         SMEM_TOTAL);

    init_kernel<<<64, 256>>>(W1);
    fused_kernel<<<dim3(NCTA_X, B_), NTHR, SMEM_TOTAL>>>(
        data, labels, b1, Wa1, ba1, Wa2, ba2, Wf1, bf1, Wf2, bf2,
        (float*)d_out);
}

// round 9
// speedup vs baseline: 1.0454x; 1.0454x over previous
#include <cuda_runtime.h>
#include <cuda_fp16.h>
#include <cstdint>

#define B_     8
#define N_     4096
#define D_     1024
#define EMB_   64
#define CLN_   10
#define TILE_M 64
#define KC_    32
#define NCHUNK (D_ / KC_)          // 32
#define NTHR   256
#define NCTA_X (N_ / TILE_M)       // 64 CTAs per batch
#define PSTRIDE 656
#define NSTAGE 3

// ---------------- device scratch (allocation-free rule) ----------------
__device__ float g_part[B_ * NCTA_X * PSTRIDE];
__device__ int   g_done[B_];                      // zero-init; self-resetting
__device__ __align__(16) __half g_W1hi[EMB_ * D_];
__device__ __align__(16) __half g_W1lo[EMB_ * D_];

// ---------------- dynamic smem layout (bytes) ----------------
#define SM_B1S    0                // 64 f
#define SM_LABS   256              // 64 int
#define SM_CSUM   512              // 2 x 640 f -> ends 5632
#define SM_STAGE  6144
// stage: Ahi 4KB | Alo 4KB | Bhi 4KB | Blo 4KB   (64 rows x 64B each)
#define ALO_OFF   4096
#define BHI_OFF   8192
#define BLO_OFF   12288
#define STAGE_SZ  16384
#define SMEM_TOTAL (SM_STAGE + NSTAGE * STAGE_SZ)   // 55296 -> 4 CTAs/SM

__device__ __forceinline__ uint32_t smem_u32(const void* p) {
    uint32_t a;
    asm("{ .reg .u64 t; cvta.to.shared.u64 t, %1; cvt.u32.u64 %0, t; }" : "=r"(a) : "l"(p));
    return a;
}
__device__ __forceinline__ uint32_t sw64(uint32_t o) { return o ^ ((o >> 3) & 0x30); }

__device__ __forceinline__ void ldmx4(uint32_t* r, uint32_t addr) {
    asm volatile("ldmatrix.sync.aligned.m8n8.x4.shared.b16 {%0,%1,%2,%3}, [%4];"
                 : "=r"(r[0]), "=r"(r[1]), "=r"(r[2]), "=r"(r[3]) : "r"(addr));
}
__device__ __forceinline__ void mma16816(float* c, const uint32_t* a, uint32_t b0, uint32_t b1) {
    asm volatile("mma.sync.aligned.m16n8k16.row.col.f32.f16.f16.f32 "
                 "{%0,%1,%2,%3}, {%4,%5,%6,%7}, {%8,%9}, {%0,%1,%2,%3};"
                 : "+f"(c[0]), "+f"(c[1]), "+f"(c[2]), "+f"(c[3])
                 : "r"(a[0]), "r"(a[1]), "r"(a[2]), "r"(a[3]), "r"(b0), "r"(b1));
}
__device__ __forceinline__ void cpasync16(uint32_t saddr, const void* gaddr) {
    asm volatile("cp.async.cg.shared.global [%0], [%1], 16;" :: "r"(saddr), "l"(gaddr));
}
__device__ __forceinline__ void sts64(uint32_t addr, uint32_t x, uint32_t y) {
    asm volatile("st.shared.v2.u32 [%0], {%1, %2};" :: "r"(addr), "r"(x), "r"(y));
}

// ---------------------------------------------------------------------------
// Kernel 0: split-convert W1 to fp16 hi/lo
// ---------------------------------------------------------------------------
__global__ void init_kernel(const float* __restrict__ W1) {
    int i4 = blockIdx.x * 256 + threadIdx.x;
    float4 v = *(const float4*)(W1 + (size_t)i4 * 4);
    __half2 h0 = __floats2half2_rn(v.x, v.y);
    __half2 h1 = __floats2half2_rn(v.z, v.w);
    float2 f0 = __half22float2(h0), f1 = __half22float2(h1);
    __half2 l0 = __floats2half2_rn(v.x - f0.x, v.y - f0.y);
    __half2 l1 = __floats2half2_rn(v.z - f1.x, v.w - f1.y);
    uint2 hv, lv;
    hv.x = *(uint32_t*)&h0; hv.y = *(uint32_t*)&h1;
    lv.x = *(uint32_t*)&l0; lv.y = *(uint32_t*)&l1;
    *(uint2*)(g_W1hi + (size_t)i4 * 4) = hv;
    *(uint2*)(g_W1lo + (size_t)i4 * 4) = lv;
}

// ---------------------------------------------------------------------------
// Fused kernel: producer-side A split-cvt into smem (done ONCE per element),
// 8 consumer warps (16 rows x 32 cols each) via ldmatrix; B via cp.async ring.
// Last CTA per batch runs the attention head.
// ---------------------------------------------------------------------------
__global__ void __launch_bounds__(NTHR, 4)
fused_kernel(const float* __restrict__ data,
             const int*   __restrict__ labels,
             const float* __restrict__ b1,
             const float* __restrict__ Wa1, const float* __restrict__ ba1,
             const float* __restrict__ Wa2, const float* __restrict__ ba2,
             const float* __restrict__ Wf1, const float* __restrict__ bf1,
             const float* __restrict__ Wf2, const float* __restrict__ bf2,
             float* __restrict__ out) {
    extern __shared__ char smem[];
    const uint32_t sb = smem_u32(smem);
    const int tid  = threadIdx.x;
    const int warp = tid >> 5;
    const int lane = tid & 31;
    const int wm   = warp & 3;        // m-group: rows wm*16..+15
    const int wn   = warp >> 2;       // n-group: cols wn*32..+31
    const int b    = blockIdx.y;
    const int bx   = blockIdx.x;
    const int p0   = bx * TILE_M;

    float* b1s  = (float*)(smem + SM_B1S);
    int*   labs = (int*)  (smem + SM_LABS);
    float* csum = (float*)(smem + SM_CSUM);

    if (tid < EMB_)   b1s[tid]  = b1[tid];
    if (tid < TILE_M) labs[tid] = labels[b * N_ + p0 + tid];
    for (int i = tid; i < 2 * CLN_ * EMB_; i += NTHR) csum[i] = 0.0f;

    const float* dbase = data + (size_t)(b * N_ + p0) * D_;

    // ---- B cp.async fill (proven R7/R8 pattern) ----
    const int b_r = tid >> 2, b_q = tid & 3;
    auto issueB = [&](int chunk) {
        const int kc = chunk * KC_;
        const uint32_t st = sb + SM_STAGE + (chunk % NSTAGE) * STAGE_SZ;
        uint32_t sw = sw64((uint32_t)(b_r * 64 + b_q * 16));
        cpasync16(st + BHI_OFF + sw, g_W1hi + (size_t)b_r * D_ + kc + b_q * 8);
        cpasync16(st + BLO_OFF + sw, g_W1lo + (size_t)b_r * D_ + kc + b_q * 8);
        asm volatile("cp.async.commit_group;");
    };

    // ---- A producer: thread covers rows (tid>>3) and (tid>>3)+32, col-unit q ----
    const int a_q = tid & 7;          // 16B (4-float) unit within 32-float chunk row
    const int a_r = tid >> 3;         // 0..31
    float4 pre[2];
    auto loadA = [&](int chunk) {
        const int kc = chunk * KC_;
        pre[0] = *(const float4*)(dbase + (size_t)a_r * D_ + kc + a_q * 4);
        pre[1] = *(const float4*)(dbase + (size_t)(a_r + 32) * D_ + kc + a_q * 4);
    };
    auto cvtStoreA = [&](int chunk) {
        const uint32_t st = sb + SM_STAGE + (chunk % NSTAGE) * STAGE_SZ;
#pragma unroll
        for (int i = 0; i < 2; i++) {
            int r = a_r + i * 32;
            float4 x = pre[i];
            __half2 h0 = __floats2half2_rn(x.x, x.y);
            __half2 h1 = __floats2half2_rn(x.z, x.w);
            float2 f0 = __half22float2(h0), f1 = __half22float2(h1);
            __half2 l0 = __floats2half2_rn(x.x - f0.x, x.y - f0.y);
            __half2 l1 = __floats2half2_rn(x.z - f1.x, x.w - f1.y);
            uint32_t sw = sw64((uint32_t)(r * 64 + a_q * 8));
            sts64(st + sw,           *(uint32_t*)&h0, *(uint32_t*)&h1);
            sts64(st + ALO_OFF + sw, *(uint32_t*)&l0, *(uint32_t*)&l1);
        }
    };

    // ---- prologue ----
    issueB(0);
    issueB(1);
    loadA(0);
    cvtStoreA(0);
    loadA(1);
    asm volatile("cp.async.wait_group 1;");
    __syncthreads();

    float acc[4][4];
#pragma unroll
    for (int nt = 0; nt < 4; nt++)
#pragma unroll
        for (int i = 0; i < 4; i++) acc[nt][i] = 0.0f;

    // A ldmatrix lane mapping (x4: {r,k0},{r+8,k0},{r,k8},{r+8,k8})
    const uint32_t a_off0 = (uint32_t)((wm * 16 + (lane & 7) + ((lane >> 3) & 1) * 8) * 64 +
                                       (lane >> 4) * 16);
    const uint32_t brow8 = (uint32_t)(((lane >> 4) & 1) * 8 + (lane & 7));
    const uint32_t bkb   = (uint32_t)(((lane >> 3) & 1) * 16);

    for (int c = 0; c < NCHUNK; c++) {
        if (c + 2 < NCHUNK) issueB(c + 2);
        else asm volatile("cp.async.commit_group;");   // uniform group count

        const uint32_t st = sb + SM_STAGE + (c % NSTAGE) * STAGE_SZ;
#pragma unroll
        for (int ks = 0; ks < 2; ks++) {
            uint32_t ah[4], al[4];
            uint32_t aoff = sw64(a_off0 + (uint32_t)(ks * 32));
            ldmx4(ah, st + aoff);
            ldmx4(al, st + ALO_OFF + aoff);
#pragma unroll
            for (int j = 0; j < 2; j++) {
                uint32_t bh[4], bl[4];
                uint32_t boff = sw64((uint32_t)(wn * 32 + j * 16 + (int)brow8) * 64 +
                                     (uint32_t)(ks * 32) + bkb);
                ldmx4(bh, st + BHI_OFF + boff);
                ldmx4(bl, st + BLO_OFF + boff);
                mma16816(acc[2 * j],     ah, bh[0], bh[1]);
                mma16816(acc[2 * j],     ah, bl[0], bl[1]);
                mma16816(acc[2 * j],     al, bh[0], bh[1]);
                mma16816(acc[2 * j + 1], ah, bh[2], bh[3]);
                mma16816(acc[2 * j + 1], ah, bl[2], bl[3]);
                mma16816(acc[2 * j + 1], al, bh[2], bh[3]);
            }
        }

        if (c + 1 < NCHUNK) {
            cvtStoreA(c + 1);                     // writes stage (c+1)%3 (free)
            if (c + 2 < NCHUNK) loadA(c + 2);     // LDG flies under next MMA phase
        }
        asm volatile("cp.async.wait_group 1;");   // B(c+1) complete
        __syncthreads();                          // A(c+1) visible; stage reads done
    }
    asm volatile("cp.async.wait_group 0;");
    __syncthreads();

    // ---- epilogue: bias + ReLU -> e-tile (64 x 66, reuse stage region) ----
    float* etile = (float*)(smem + SM_STAGE);
    {
        int r0 = wm * 16 + (lane >> 2);
        int cq = 2 * (lane & 3);
#pragma unroll
        for (int j = 0; j < 2; j++)
#pragma unroll
            for (int s = 0; s < 2; s++) {
                int col = wn * 32 + j * 16 + s * 8 + cq;
                int ai  = 2 * j + s;
                float bv0 = b1s[col], bv1 = b1s[col + 1];
                etile[r0 * 66 + col]           = fmaxf(acc[ai][0] + bv0, 0.0f);
                etile[r0 * 66 + col + 1]       = fmaxf(acc[ai][1] + bv1, 0.0f);
                etile[(r0 + 8) * 66 + col]     = fmaxf(acc[ai][2] + bv0, 0.0f);
                etile[(r0 + 8) * 66 + col + 1] = fmaxf(acc[ai][3] + bv1, 0.0f);
            }
    }
    __syncthreads();

    {   // split-row segment reduction, no atomics (threads 0-63 and 128-191)
        if (((tid >> 6) & 1) == 0) {
            int half = tid >> 7;
            int e    = tid & 63;
            float* cs = csum + half * (CLN_ * EMB_);
            int rbase = half * 32;
            for (int r = 0; r < 32; r++) {
                int row = rbase + r;
                cs[labs[row] * EMB_ + e] += etile[row * 66 + e];
            }
        }
    }
    __syncthreads();

    float* prow = g_part + ((size_t)b * NCTA_X + bx) * PSTRIDE;
    for (int i = tid; i < CLN_ * EMB_; i += NTHR)
        prow[i] = csum[i] + csum[CLN_ * EMB_ + i];
    if (tid < CLN_) {
        int cnt = 0;
        for (int r = 0; r < TILE_M; r++) cnt += (labs[r] == tid);
        prow[640 + tid] = (float)cnt;
    }
    __threadfence();
    __syncthreads();

    // ---- last CTA of this batch runs the head ----
    __shared__ int s_last;
    if (tid == 0) s_last = (atomicAdd(&g_done[b], 1) == NCTA_X - 1) ? 1 : 0;
    __syncthreads();
    if (!s_last) return;
    __threadfence();

    float* hc    = (float*)(smem + SM_STAGE);
    float* h     = hc + 656;
    float* u     = h + 640;
    float* score = u + 320;
    float* Avec  = score + 16;
    float* mask  = Avec + 16;
    float* Mv    = mask + 16;
    float* f     = Mv + 64;

    for (int i = tid; i < 650; i += NTHR) {
        float s = 0.0f;
        const float* base = g_part + (size_t)b * NCTA_X * PSTRIDE + i;
#pragma unroll
        for (int j = 0; j < NCTA_X; j++) s += base[j * PSTRIDE];
        hc[i] = s;
    }
    __syncthreads();

    if (tid < EMB_) {
        for (int c = 0; c < CLN_; c++)
            h[c * EMB_ + tid] = hc[c * EMB_ + tid] / fmaxf(hc[640 + c], 1.0f);
    }
    if (tid < CLN_) mask[tid] = (hc[640 + tid] > 0.0f) ? 1.0f : 0.0f;
    __syncthreads();

    if (tid < 32) {
        for (int c = 0; c < CLN_; c++) {
            float s = ba1[tid];
            for (int e = 0; e < EMB_; e++) s += h[c * EMB_ + e] * Wa1[tid * EMB_ + e];
            u[c * 32 + tid] = tanhf(s);
        }
    }
    __syncthreads();

    if (tid < CLN_) {
        float s = ba2[0];
        for (int k = 0; k < 32; k++) s += u[tid * 32 + k] * Wa2[k];
        score[tid] = s;
    }
    __syncthreads();

    if (tid == 0) {
        float xmax = -1e30f;
        for (int c = 0; c < CLN_; c++) {
            float xm = score[c] * mask[c] + (1.0f - 1.0f / (mask[c] + 1e-5f));
            xmax = fmaxf(xmax, xm);
        }
        float ssum = 0.0f;
        for (int c = 0; c < CLN_; c++) {
            float ex = expf(score[c] - xmax) * mask[c];
            Avec[c] = ex;
            ssum += ex;
        }
        for (int c = 0; c < CLN_; c++) Avec[c] /= ssum;
    }
    __syncthreads();

    if (tid < EMB_) {
        float m = 0.0f;
        for (int c = 0; c < CLN_; c++) m += Avec[c] * h[c * EMB_ + tid];
        Mv[tid] = m;
    }
    __syncthreads();

    if (tid < 32) {
        float s = bf1[tid];
        for (int e = 0; e < EMB_; e++) s += Mv[e] * Wf1[tid * EMB_ + e];
        f[tid] = fmaxf(s, 0.0f);
    }
    __syncthreads();

    if (tid == 0) {
        float s = bf2[0];
        for (int k = 0; k < 32; k++) s += f[k] * Wf2[k];
        out[b] = s;
        g_done[b] = 0;      // reset for next graph replay
    }
}

// ---------------------------------------------------------------------------
extern "C" void kernel_launch(void* const* d_in, const int* in_sizes, int n_in,
                              void* d_out, int out_size) {
    const float* data   = (const float*)d_in[0];
    const int*   labels = (const int*)  d_in[1];
    const float* W1     = (const float*)d_in[2];
    const float* b1     = (const float*)d_in[3];
    const float* Wa1    = (const float*)d_in[4];
    const float* ba1    = (const float*)d_in[5];
    const float* Wa2    = (const float*)d_in[6];
    const float* ba2    = (const float*)d_in[7];
    const float* Wf1    = (const float*)d_in[8];
    const float* bf1    = (const float*)d_in[9];
    const float* Wf2    = (const float*)d_in[10];
    const float* bf2    = (const float*)d_in[11];

    cudaFuncSetAttribute(fused_kernel, cudaFuncAttributeMaxDynamicSharedMemorySize,
                         SMEM_TOTAL);

    init_kernel<<<64, 256>>>(W1);
    fused_kernel<<<dim3(NCTA_X, B_), NTHR, SMEM_TOTAL>>>(
        data, labels, b1, Wa1, ba1, Wa2, ba2, Wf1, bf1, Wf2, bf2,
        (float*)d_out);
}